// round 10
// baseline (speedup 1.0000x reference)
#include <cuda_runtime.h>
#include <cuda_bf16.h>
#include <cstdint>

// ---------------------------------------------------------------------------
// Problem dims (fixed)
// ---------------------------------------------------------------------------
#define M_DIM 16384
#define D_DIM 1024

// GEMM tiling
#define BM 128
#define BN 128
#define BK 64                        // bf16 elements per K-stage (=128B rows)
#define NSTAGES (D_DIM / BK)         // 16
#define NBUF 3
#define NTH 256                      // 8 warps (2x4 grid, 64x32 warp tiles)

// SMEM stage layout (bytes): rows of 128B, SW128 xor-swizzled
#define A_SZ (BM * 128)              // 16384
#define OFF_AH 0
#define OFF_AL (A_SZ)
#define OFF_BH (2 * A_SZ)
#define OFF_BL (3 * A_SZ)
#define STAGE_BYTES (4 * A_SZ)       // 65536
#define SMEM_TOTAL (1024 + NBUF * STAGE_BYTES)   // 197632

// ---------------------------------------------------------------------------
// Scratch (__device__ globals; no allocation allowed)
// ---------------------------------------------------------------------------
__device__ __align__(256) __nv_bfloat16 g_xh[(size_t)M_DIM * D_DIM];
__device__ __align__(256) __nv_bfloat16 g_xl[(size_t)M_DIM * D_DIM];
__device__ __align__(256) __nv_bfloat16 g_a0h[(size_t)M_DIM * D_DIM];
__device__ __align__(256) __nv_bfloat16 g_a0l[(size_t)M_DIM * D_DIM];
__device__ __align__(256) __nv_bfloat16 g_a1h[(size_t)M_DIM * D_DIM];
__device__ __align__(256) __nv_bfloat16 g_a1l[(size_t)M_DIM * D_DIM];
__device__ __align__(256) __nv_bfloat16 g_wsh[(size_t)4 * D_DIM * D_DIM];
__device__ __align__(256) __nv_bfloat16 g_wsl[(size_t)4 * D_DIM * D_DIM];
__device__ __align__(256) __nv_bfloat16 g_woh[(size_t)D_DIM * D_DIM];
__device__ __align__(256) __nv_bfloat16 g_wol[(size_t)D_DIM * D_DIM];
__device__ float g_rowsum[M_DIM];

// ---------------------------------------------------------------------------
// PTX helpers (all baseline compute_80-level)
// ---------------------------------------------------------------------------
__device__ __forceinline__ uint32_t smem_u32(const void* p) {
    uint32_t a;
    asm("{ .reg .u64 t; cvta.to.shared.u64 t, %1; cvt.u32.u64 %0, t; }"
        : "=r"(a) : "l"(p));
    return a;
}
__device__ __forceinline__ void cpa16(uint32_t dst, const void* src) {
    asm volatile("cp.async.cg.shared.global [%0], [%1], 16;" :: "r"(dst), "l"(src));
}
#define CP_COMMIT() asm volatile("cp.async.commit_group;" ::: "memory")
#define CP_WAIT1()  asm volatile("cp.async.wait_group 1;" ::: "memory")

__device__ __forceinline__ uint32_t swz(uint32_t off) {
    return off ^ ((off >> 3) & 0x70);
}
__device__ __forceinline__ void ldmx4(uint32_t* r, uint32_t addr) {
    asm volatile("ldmatrix.sync.aligned.m8n8.x4.shared.b16 {%0,%1,%2,%3}, [%4];"
                 : "=r"(r[0]), "=r"(r[1]), "=r"(r[2]), "=r"(r[3]) : "r"(addr));
}
__device__ __forceinline__ void mma16816(float* c, const uint32_t* a,
                                         const uint32_t* b) {
    asm volatile(
        "mma.sync.aligned.m16n8k16.row.col.f32.bf16.bf16.f32 "
        "{%0,%1,%2,%3}, {%4,%5,%6,%7}, {%8,%9}, {%0,%1,%2,%3};"
        : "+f"(c[0]), "+f"(c[1]), "+f"(c[2]), "+f"(c[3])
        : "r"(a[0]), "r"(a[1]), "r"(a[2]), "r"(a[3]), "r"(b[0]), "r"(b[1]));
}

// ---------------------------------------------------------------------------
// Small kernels
// ---------------------------------------------------------------------------
__global__ void split_kernel(const float* __restrict__ s,
                             __nv_bfloat16* __restrict__ h,
                             __nv_bfloat16* __restrict__ l, int n4) {
    int i = blockIdx.x * blockDim.x + threadIdx.x;
    if (i >= n4) return;
    float4 v = reinterpret_cast<const float4*>(s)[i];
    __nv_bfloat16 h0 = __float2bfloat16_rn(v.x);
    __nv_bfloat16 h1 = __float2bfloat16_rn(v.y);
    __nv_bfloat16 h2 = __float2bfloat16_rn(v.z);
    __nv_bfloat16 h3 = __float2bfloat16_rn(v.w);
    __nv_bfloat16 l0 = __float2bfloat16_rn(v.x - __bfloat162float(h0));
    __nv_bfloat16 l1 = __float2bfloat16_rn(v.y - __bfloat162float(h1));
    __nv_bfloat16 l2 = __float2bfloat16_rn(v.z - __bfloat162float(h2));
    __nv_bfloat16 l3 = __float2bfloat16_rn(v.w - __bfloat162float(h3));
    __nv_bfloat162 hp0(h0, h1), hp1(h2, h3), lp0(l0, l1), lp1(l2, l3);
    reinterpret_cast<__nv_bfloat162*>(h)[i * 2 + 0] = hp0;
    reinterpret_cast<__nv_bfloat162*>(h)[i * 2 + 1] = hp1;
    reinterpret_cast<__nv_bfloat162*>(l)[i * 2 + 0] = lp0;
    reinterpret_cast<__nv_bfloat162*>(l)[i * 2 + 1] = lp1;
}

__global__ void splitx_rowsum(const float* __restrict__ x,
                              __nv_bfloat16* __restrict__ xh,
                              __nv_bfloat16* __restrict__ xl,
                              float* __restrict__ rs) {
    int row  = blockIdx.x * 8 + (threadIdx.x >> 5);
    int lane = threadIdx.x & 31;
    const float4* xr = reinterpret_cast<const float4*>(x + (size_t)row * D_DIM);
    __nv_bfloat162* dh = reinterpret_cast<__nv_bfloat162*>(xh + (size_t)row * D_DIM);
    __nv_bfloat162* dl = reinterpret_cast<__nv_bfloat162*>(xl + (size_t)row * D_DIM);
    float s = 0.f;
#pragma unroll
    for (int i = 0; i < 8; i++) {
        float4 v = xr[lane + i * 32];
        s += v.x + v.y + v.z + v.w;
        __nv_bfloat16 h0 = __float2bfloat16_rn(v.x);
        __nv_bfloat16 h1 = __float2bfloat16_rn(v.y);
        __nv_bfloat16 h2 = __float2bfloat16_rn(v.z);
        __nv_bfloat16 h3 = __float2bfloat16_rn(v.w);
        __nv_bfloat16 l0 = __float2bfloat16_rn(v.x - __bfloat162float(h0));
        __nv_bfloat16 l1 = __float2bfloat16_rn(v.y - __bfloat162float(h1));
        __nv_bfloat16 l2 = __float2bfloat16_rn(v.z - __bfloat162float(h2));
        __nv_bfloat16 l3 = __float2bfloat16_rn(v.w - __bfloat162float(h3));
        dh[(lane + i * 32) * 2 + 0] = __nv_bfloat162(h0, h1);
        dh[(lane + i * 32) * 2 + 1] = __nv_bfloat162(h2, h3);
        dl[(lane + i * 32) * 2 + 0] = __nv_bfloat162(l0, l1);
        dl[(lane + i * 32) * 2 + 1] = __nv_bfloat162(l2, l3);
    }
#pragma unroll
    for (int o = 16; o > 0; o >>= 1) s += __shfl_xor_sync(0xffffffffu, s, o);
    if (lane == 0) rs[row] = s;
}

// ---------------------------------------------------------------------------
// HMMA GEMM, 8 warps, 64x32 warp tiles, 3-term split-bf16, fused epilogue.
// ks-level fragment double-buffering + cp.async spread across ks iterations.
// ---------------------------------------------------------------------------
template <int MODE>
__global__ __launch_bounds__(NTH, 1)
void gemm_mma(const __nv_bfloat16* __restrict__ Ah, const __nv_bfloat16* __restrict__ Al,
              const __nv_bfloat16* __restrict__ Wh, const __nv_bfloat16* __restrict__ Wl,
              const float* __restrict__ bias,
              __nv_bfloat16* __restrict__ Oh, __nv_bfloat16* __restrict__ Ol,
              float* __restrict__ Of,
              const float* __restrict__ x, const float* __restrict__ rowsum)
{
    extern __shared__ char smem_raw[];
    uint32_t sb = smem_u32(smem_raw);
    sb = (sb + 1023u) & ~1023u;

    const int tid  = threadIdx.x;
    const int wid  = tid >> 5;
    const int lane = tid & 31;
    const int wm   = wid >> 2;          // 0..1  (64 rows each)
    const int wn   = wid & 3;           // 0..3  (32 cols each)
    const int n0   = blockIdx.x * BN;
    const int m0   = blockIdx.y * BM;

    // ---- hoisted loader addressing (loop-invariant per thread) ----
    const int lc = tid & 7;
    uint32_t swo[4];
    size_t gaB[4], gbB[4];
#pragma unroll
    for (int i = 0; i < 4; i++) {
        int r = (tid >> 3) + i * 32;
        swo[i] = swz((uint32_t)(r * 128 + lc * 16));
        gaB[i] = (size_t)(m0 + r) * D_DIM + lc * 8;
        gbB[i] = (size_t)(n0 + r) * D_DIM + lc * 8;
    }

    auto load_stage = [&](int s) {
        const uint32_t base = sb + (uint32_t)(s % NBUF) * STAGE_BYTES;
        const int kt = s * BK;
#pragma unroll
        for (int i = 0; i < 4; i++) {
            cpa16(base + OFF_AH + swo[i], Ah + gaB[i] + kt);
            cpa16(base + OFF_AL + swo[i], Al + gaB[i] + kt);
            cpa16(base + OFF_BH + swo[i], Wh + gbB[i] + kt);
            cpa16(base + OFF_BL + swo[i], Wl + gbB[i] + kt);
        }
    };

    float acc[4][4][4];
#pragma unroll
    for (int i = 0; i < 4; i++)
#pragma unroll
        for (int j = 0; j < 4; j++)
#pragma unroll
            for (int q = 0; q < 4; q++) acc[i][j][q] = 0.f;

    load_stage(0); CP_COMMIT();
    load_stage(1); CP_COMMIT();

    // ldmatrix per-lane address components
    const uint32_t a_row = wm * 64 + (lane & 15);
    const uint32_t a_k   = (uint32_t)(lane >> 4) * 8;
    const uint32_t b_row = wn * 32 + ((uint32_t)(lane >> 4) * 8) + (lane & 7);
    const uint32_t b_k   = (uint32_t)((lane >> 3) & 1) * 8;

    // double-buffered fragment banks
    uint32_t ah[2][4][4], al[2][4][4], bh[2][2][4], bl[2][2][4];

#pragma unroll 1
    for (int s = 0; s < NSTAGES; s++) {
        CP_WAIT1();                 // stage s resident (s+1 may be in flight)
        __syncthreads();            // data visible; stage s-1 readers retired

        const uint32_t base = sb + (uint32_t)(s % NBUF) * STAGE_BYTES;
        const bool pf = (s + 2 < NSTAGES);
        const uint32_t pbase = sb + (uint32_t)((s + 2) % NBUF) * STAGE_BYTES;
        const int pkt = (s + 2) * BK;

        // preload ks=0 fragments into bank 0
        {
#pragma unroll
            for (int mt = 0; mt < 4; mt++) {
                uint32_t sw = swz((a_row + mt * 16) * 128 + a_k * 2);
                ldmx4(ah[0][mt], base + OFF_AH + sw);
                ldmx4(al[0][mt], base + OFF_AL + sw);
            }
#pragma unroll
            for (int nb = 0; nb < 2; nb++) {
                uint32_t sw = swz((b_row + nb * 16) * 128 + b_k * 2);
                ldmx4(bh[0][nb], base + OFF_BH + sw);
                ldmx4(bl[0][nb], base + OFF_BL + sw);
            }
        }

#pragma unroll
        for (int ks = 0; ks < 4; ks++) {
            const int cur = ks & 1;
            const int nxt = cur ^ 1;
            // preload ks+1 fragments into the other bank (overlaps MMAs below)
            if (ks < 3) {
                const uint32_t kk = (ks + 1) * 16;
#pragma unroll
                for (int mt = 0; mt < 4; mt++) {
                    uint32_t sw = swz((a_row + mt * 16) * 128 + (kk + a_k) * 2);
                    ldmx4(ah[nxt][mt], base + OFF_AH + sw);
                    ldmx4(al[nxt][mt], base + OFF_AL + sw);
                }
#pragma unroll
                for (int nb = 0; nb < 2; nb++) {
                    uint32_t sw = swz((b_row + nb * 16) * 128 + (kk + b_k) * 2);
                    ldmx4(bh[nxt][nb], base + OFF_BH + sw);
                    ldmx4(bl[nxt][nb], base + OFF_BL + sw);
                }
            }
            // spread global prefetch of stage s+2: one chunk per ks
            if (pf) {
                cpa16(pbase + OFF_AH + swo[ks], Ah + gaB[ks] + pkt);
                cpa16(pbase + OFF_AL + swo[ks], Al + gaB[ks] + pkt);
                cpa16(pbase + OFF_BH + swo[ks], Wh + gbB[ks] + pkt);
                cpa16(pbase + OFF_BL + swo[ks], Wl + gbB[ks] + pkt);
            }
            // 48 MMAs on current bank
#pragma unroll
            for (int mt = 0; mt < 4; mt++)
#pragma unroll
                for (int nt = 0; nt < 4; nt++) {
                    const uint32_t* bhp = &bh[cur][nt >> 1][(nt & 1) * 2];
                    const uint32_t* blp = &bl[cur][nt >> 1][(nt & 1) * 2];
                    mma16816(acc[mt][nt], ah[cur][mt], bhp);
                    mma16816(acc[mt][nt], ah[cur][mt], blp);
                    mma16816(acc[mt][nt], al[cur][mt], bhp);
                }
        }
        if (pf) CP_COMMIT();
    }

    // ---- epilogue ----
    const int qrow = lane >> 2;          // 0..7
    const int qcol = (lane & 3) * 2;     // 0,2,4,6
#pragma unroll
    for (int mt = 0; mt < 4; mt++) {
#pragma unroll
        for (int half = 0; half < 2; half++) {
            const int gm = m0 + wm * 64 + mt * 16 + qrow + half * 8;
            float rsv = 0.f;
            if (MODE == 1) rsv = rowsum[gm];
#pragma unroll
            for (int nt = 0; nt < 4; nt++) {
                const int gn = n0 + wn * 32 + nt * 8 + qcol;
                const float2 bv = *reinterpret_cast<const float2*>(bias + gn);
                float v0 = acc[mt][nt][half * 2 + 0] + bv.x;
                float v1 = acc[mt][nt][half * 2 + 1] + bv.y;
                if (MODE == 2) {
                    *reinterpret_cast<float2*>(Of + (size_t)gm * D_DIM + gn) =
                        make_float2(v0, v1);
                } else {
                    v0 = fmaxf(v0, 0.f);
                    v1 = fmaxf(v1, 0.f);
                    if (MODE == 1) {
                        const float2 xv = *reinterpret_cast<const float2*>(
                            x + (size_t)gm * D_DIM + gn);
                        v0 = (v0 + fmaxf(xv.x * rsv, 0.f)) * 0.5f;
                        v1 = (v1 + fmaxf(xv.y * rsv, 0.f)) * 0.5f;
                    }
                    __nv_bfloat16 h0 = __float2bfloat16_rn(v0);
                    __nv_bfloat16 h1 = __float2bfloat16_rn(v1);
                    __nv_bfloat16 l0 = __float2bfloat16_rn(v0 - __bfloat162float(h0));
                    __nv_bfloat16 l1 = __float2bfloat16_rn(v1 - __bfloat162float(h1));
                    __nv_bfloat162 hp(h0, h1), lp(l0, l1);
                    *reinterpret_cast<__nv_bfloat162*>(Oh + (size_t)gm * D_DIM + gn) = hp;
                    *reinterpret_cast<__nv_bfloat162*>(Ol + (size_t)gm * D_DIM + gn) = lp;
                }
            }
        }
    }
}

// ---------------------------------------------------------------------------
// Launch
// ---------------------------------------------------------------------------
extern "C" void kernel_launch(void* const* d_in, const int* in_sizes, int n_in,
                              void* d_out, int out_size) {
    const float* x  = (const float*)d_in[0];
    const float* Ws = (const float*)d_in[1];   // (4, D, D)
    const float* bs = (const float*)d_in[2];   // (4, D)
    const float* Wo = (const float*)d_in[3];   // (D, D)
    const float* bo = (const float*)d_in[4];   // (D,)
    float* out = (float*)d_out;

    __nv_bfloat16 *xh, *xl, *a0h, *a0l, *a1h, *a1l, *wsh, *wsl, *woh, *wol;
    float* rs;
    cudaGetSymbolAddress((void**)&xh,  g_xh);
    cudaGetSymbolAddress((void**)&xl,  g_xl);
    cudaGetSymbolAddress((void**)&a0h, g_a0h);
    cudaGetSymbolAddress((void**)&a0l, g_a0l);
    cudaGetSymbolAddress((void**)&a1h, g_a1h);
    cudaGetSymbolAddress((void**)&a1l, g_a1l);
    cudaGetSymbolAddress((void**)&wsh, g_wsh);
    cudaGetSymbolAddress((void**)&wsl, g_wsl);
    cudaGetSymbolAddress((void**)&woh, g_woh);
    cudaGetSymbolAddress((void**)&wol, g_wol);
    cudaGetSymbolAddress((void**)&rs,  g_rowsum);

    cudaFuncSetAttribute(gemm_mma<0>, cudaFuncAttributeMaxDynamicSharedMemorySize, SMEM_TOTAL);
    cudaFuncSetAttribute(gemm_mma<1>, cudaFuncAttributeMaxDynamicSharedMemorySize, SMEM_TOTAL);
    cudaFuncSetAttribute(gemm_mma<2>, cudaFuncAttributeMaxDynamicSharedMemorySize, SMEM_TOTAL);

    const size_t DD = (size_t)D_DIM * D_DIM;

    splitx_rowsum<<<M_DIM / 8, 256>>>(x, xh, xl, rs);
    split_kernel<<<(int)(4 * DD / 4 / 256), 256>>>(Ws, wsh, wsl, (int)(4 * DD / 4));
    split_kernel<<<(int)(DD / 4 / 256), 256>>>(Wo, woh, wol, (int)(DD / 4));

    dim3 grid(D_DIM / BN, M_DIM / BM);   // (8, 128)

    gemm_mma<0><<<grid, NTH, SMEM_TOTAL>>>(xh,  xl,  wsh + 0 * DD, wsl + 0 * DD,
                                           bs + 0 * D_DIM, a0h, a0l, nullptr, nullptr, nullptr);
    gemm_mma<0><<<grid, NTH, SMEM_TOTAL>>>(a0h, a0l, wsh + 1 * DD, wsl + 1 * DD,
                                           bs + 1 * D_DIM, a1h, a1l, nullptr, nullptr, nullptr);
    gemm_mma<0><<<grid, NTH, SMEM_TOTAL>>>(a1h, a1l, wsh + 2 * DD, wsl + 2 * DD,
                                           bs + 2 * D_DIM, a0h, a0l, nullptr, nullptr, nullptr);
    gemm_mma<1><<<grid, NTH, SMEM_TOTAL>>>(a0h, a0l, wsh + 3 * DD, wsl + 3 * DD,
                                           bs + 3 * D_DIM, a1h, a1l, nullptr, x, rs);
    gemm_mma<2><<<grid, NTH, SMEM_TOTAL>>>(a1h, a1l, woh, wol,
                                           bo, nullptr, nullptr, out, nullptr, nullptr);
}

// round 11
// speedup vs baseline: 3.2756x; 3.2756x over previous
#include <cuda_runtime.h>
#include <cuda_fp16.h>
#include <cstdint>

// ---------------------------------------------------------------------------
// Problem dims (fixed)
// ---------------------------------------------------------------------------
#define M_DIM 16384
#define D_DIM 1024

// GEMM tiling
#define BM 128
#define BN 128
#define BK 64                        // fp16 elements per K-stage (=128B rows)
#define NSTAGES (D_DIM / BK)         // 16
#define NBUF 3
#define NTH 256                      // 8 warps (2x4 grid, 64x32 warp tiles)

// SMEM stage layout (bytes): rows of 128B, SW128 xor-swizzled
#define A_SZ (BM * 128)              // 16384
#define OFF_A 0
#define OFF_B (A_SZ)
#define STAGE_BYTES (2 * A_SZ)       // 32768
#define SMEM_TOTAL (1024 + NBUF * STAGE_BYTES)   // 99328

// ---------------------------------------------------------------------------
// Scratch (__device__ globals; no allocation allowed)
// ---------------------------------------------------------------------------
__device__ __align__(256) __half g_x16[(size_t)M_DIM * D_DIM];
__device__ __align__(256) __half g_a0[(size_t)M_DIM * D_DIM];
__device__ __align__(256) __half g_a1[(size_t)M_DIM * D_DIM];
__device__ __align__(256) __half g_ws[(size_t)4 * D_DIM * D_DIM];
__device__ __align__(256) __half g_wo[(size_t)D_DIM * D_DIM];
__device__ float g_rowsum[M_DIM];

// ---------------------------------------------------------------------------
// PTX helpers (all baseline compute_80-level)
// ---------------------------------------------------------------------------
__device__ __forceinline__ uint32_t smem_u32(const void* p) {
    uint32_t a;
    asm("{ .reg .u64 t; cvta.to.shared.u64 t, %1; cvt.u32.u64 %0, t; }"
        : "=r"(a) : "l"(p));
    return a;
}
__device__ __forceinline__ void cpa16(uint32_t dst, const void* src) {
    asm volatile("cp.async.cg.shared.global [%0], [%1], 16;" :: "r"(dst), "l"(src));
}
#define CP_COMMIT() asm volatile("cp.async.commit_group;" ::: "memory")
#define CP_WAIT1()  asm volatile("cp.async.wait_group 1;" ::: "memory")

__device__ __forceinline__ uint32_t swz(uint32_t off) {
    return off ^ ((off >> 3) & 0x70);
}
__device__ __forceinline__ void ldmx4(uint32_t* r, uint32_t addr) {
    asm volatile("ldmatrix.sync.aligned.m8n8.x4.shared.b16 {%0,%1,%2,%3}, [%4];"
                 : "=r"(r[0]), "=r"(r[1]), "=r"(r[2]), "=r"(r[3]) : "r"(addr));
}
__device__ __forceinline__ void mma16816(float* c, const uint32_t* a,
                                         const uint32_t* b) {
    asm volatile(
        "mma.sync.aligned.m16n8k16.row.col.f32.f16.f16.f32 "
        "{%0,%1,%2,%3}, {%4,%5,%6,%7}, {%8,%9}, {%0,%1,%2,%3};"
        : "+f"(c[0]), "+f"(c[1]), "+f"(c[2]), "+f"(c[3])
        : "r"(a[0]), "r"(a[1]), "r"(a[2]), "r"(a[3]), "r"(b[0]), "r"(b[1]));
}

// ---------------------------------------------------------------------------
// Small kernels: fp32 -> fp16 conversion
// ---------------------------------------------------------------------------
__global__ void conv_kernel(const float* __restrict__ s,
                            __half* __restrict__ h, int n4) {
    int i = blockIdx.x * blockDim.x + threadIdx.x;
    if (i >= n4) return;
    float4 v = reinterpret_cast<const float4*>(s)[i];
    __half2 p0 = __floats2half2_rn(v.x, v.y);
    __half2 p1 = __floats2half2_rn(v.z, v.w);
    reinterpret_cast<__half2*>(h)[i * 2 + 0] = p0;
    reinterpret_cast<__half2*>(h)[i * 2 + 1] = p1;
}

// Fused: convert x to fp16 AND compute rowsum — one read of x.
__global__ void convx_rowsum(const float* __restrict__ x,
                             __half* __restrict__ xh,
                             float* __restrict__ rs) {
    int row  = blockIdx.x * 8 + (threadIdx.x >> 5);
    int lane = threadIdx.x & 31;
    const float4* xr = reinterpret_cast<const float4*>(x + (size_t)row * D_DIM);
    __half2* dh = reinterpret_cast<__half2*>(xh + (size_t)row * D_DIM);
    float s = 0.f;
#pragma unroll
    for (int i = 0; i < 8; i++) {
        float4 v = xr[lane + i * 32];
        s += v.x + v.y + v.z + v.w;
        dh[(lane + i * 32) * 2 + 0] = __floats2half2_rn(v.x, v.y);
        dh[(lane + i * 32) * 2 + 1] = __floats2half2_rn(v.z, v.w);
    }
#pragma unroll
    for (int o = 16; o > 0; o >>= 1) s += __shfl_xor_sync(0xffffffffu, s, o);
    if (lane == 0) rs[row] = s;
}

// ---------------------------------------------------------------------------
// HMMA GEMM, 8 warps, 64x32 warp tiles, single-term fp16, fused epilogue.
// MODE 0: relu(acc+b) -> fp16;  MODE 1: +interaction -> fp16;  MODE 2: fp32
// ---------------------------------------------------------------------------
template <int MODE>
__global__ __launch_bounds__(NTH, 1)
void gemm_mma(const __half* __restrict__ A, const __half* __restrict__ W,
              const float* __restrict__ bias,
              __half* __restrict__ Oh, float* __restrict__ Of,
              const float* __restrict__ x, const float* __restrict__ rowsum)
{
    extern __shared__ char smem_raw[];
    uint32_t sb = smem_u32(smem_raw);
    sb = (sb + 1023u) & ~1023u;

    const int tid  = threadIdx.x;
    const int wid  = tid >> 5;
    const int lane = tid & 31;
    const int wm   = wid >> 2;          // 0..1  (64 rows each)
    const int wn   = wid & 3;           // 0..3  (32 cols each)
    const int n0   = blockIdx.x * BN;
    const int m0   = blockIdx.y * BM;

    // ---- hoisted loader addressing (loop-invariant per thread) ----
    const int lc = tid & 7;
    uint32_t swo[4];
    size_t gaB[4], gbB[4];
#pragma unroll
    for (int i = 0; i < 4; i++) {
        int r = (tid >> 3) + i * 32;
        swo[i] = swz((uint32_t)(r * 128 + lc * 16));
        gaB[i] = (size_t)(m0 + r) * D_DIM + lc * 8;
        gbB[i] = (size_t)(n0 + r) * D_DIM + lc * 8;
    }

    auto load_stage = [&](int s) {
        const uint32_t base = sb + (uint32_t)(s % NBUF) * STAGE_BYTES;
        const int kt = s * BK;
#pragma unroll
        for (int i = 0; i < 4; i++) {
            cpa16(base + OFF_A + swo[i], A + gaB[i] + kt);
            cpa16(base + OFF_B + swo[i], W + gbB[i] + kt);
        }
    };

    float acc[4][4][4];
#pragma unroll
    for (int i = 0; i < 4; i++)
#pragma unroll
        for (int j = 0; j < 4; j++)
#pragma unroll
            for (int q = 0; q < 4; q++) acc[i][j][q] = 0.f;

    load_stage(0); CP_COMMIT();
    load_stage(1); CP_COMMIT();

    // ldmatrix per-lane address components
    const uint32_t a_row = wm * 64 + (lane & 15);
    const uint32_t a_k   = (uint32_t)(lane >> 4) * 8;
    const uint32_t b_row = wn * 32 + ((uint32_t)(lane >> 4) * 8) + (lane & 7);
    const uint32_t b_k   = (uint32_t)((lane >> 3) & 1) * 8;

#pragma unroll 1
    for (int s = 0; s < NSTAGES; s++) {
        CP_WAIT1();                 // stage s resident (s+1 may be in flight)
        __syncthreads();            // data visible; stage s-1 readers retired

        const uint32_t base = sb + (uint32_t)(s % NBUF) * STAGE_BYTES;
#pragma unroll
        for (int ks = 0; ks < 4; ks++) {
            const uint32_t kk = ks * 16;
            uint32_t ah[4][4], bh[2][4];
#pragma unroll
            for (int mt = 0; mt < 4; mt++) {
                uint32_t sw = swz((a_row + mt * 16) * 128 + (kk + a_k) * 2);
                ldmx4(ah[mt], base + OFF_A + sw);
            }
#pragma unroll
            for (int nb = 0; nb < 2; nb++) {
                uint32_t sw = swz((b_row + nb * 16) * 128 + (kk + b_k) * 2);
                ldmx4(bh[nb], base + OFF_B + sw);
            }
#pragma unroll
            for (int mt = 0; mt < 4; mt++)
#pragma unroll
                for (int nt = 0; nt < 4; nt++) {
                    mma16816(acc[mt][nt], ah[mt], &bh[nt >> 1][(nt & 1) * 2]);
                }
        }

        // Issue next prefetch AFTER compute (buffer (s+2)%3 freed at barrier)
        if (s + 2 < NSTAGES) { load_stage(s + 2); CP_COMMIT(); }
    }

    // ---- epilogue ----
    const int qrow = lane >> 2;          // 0..7
    const int qcol = (lane & 3) * 2;     // 0,2,4,6
#pragma unroll
    for (int mt = 0; mt < 4; mt++) {
#pragma unroll
        for (int half = 0; half < 2; half++) {
            const int gm = m0 + wm * 64 + mt * 16 + qrow + half * 8;
            float rsv = 0.f;
            if (MODE == 1) rsv = rowsum[gm];
#pragma unroll
            for (int nt = 0; nt < 4; nt++) {
                const int gn = n0 + wn * 32 + nt * 8 + qcol;
                const float2 bv = *reinterpret_cast<const float2*>(bias + gn);
                float v0 = acc[mt][nt][half * 2 + 0] + bv.x;
                float v1 = acc[mt][nt][half * 2 + 1] + bv.y;
                if (MODE == 2) {
                    *reinterpret_cast<float2*>(Of + (size_t)gm * D_DIM + gn) =
                        make_float2(v0, v1);
                } else {
                    v0 = fmaxf(v0, 0.f);
                    v1 = fmaxf(v1, 0.f);
                    if (MODE == 1) {
                        const float2 xv = *reinterpret_cast<const float2*>(
                            x + (size_t)gm * D_DIM + gn);
                        v0 = (v0 + fmaxf(xv.x * rsv, 0.f)) * 0.5f;
                        v1 = (v1 + fmaxf(xv.y * rsv, 0.f)) * 0.5f;
                    }
                    *reinterpret_cast<__half2*>(Oh + (size_t)gm * D_DIM + gn) =
                        __floats2half2_rn(v0, v1);
                }
            }
        }
    }
}

// ---------------------------------------------------------------------------
// Launch
// ---------------------------------------------------------------------------
extern "C" void kernel_launch(void* const* d_in, const int* in_sizes, int n_in,
                              void* d_out, int out_size) {
    const float* x  = (const float*)d_in[0];
    const float* Ws = (const float*)d_in[1];   // (4, D, D)
    const float* bs = (const float*)d_in[2];   // (4, D)
    const float* Wo = (const float*)d_in[3];   // (D, D)
    const float* bo = (const float*)d_in[4];   // (D,)
    float* out = (float*)d_out;

    __half *x16, *a0, *a1, *ws, *wo;
    float* rs;
    cudaGetSymbolAddress((void**)&x16, g_x16);
    cudaGetSymbolAddress((void**)&a0,  g_a0);
    cudaGetSymbolAddress((void**)&a1,  g_a1);
    cudaGetSymbolAddress((void**)&ws,  g_ws);
    cudaGetSymbolAddress((void**)&wo,  g_wo);
    cudaGetSymbolAddress((void**)&rs,  g_rowsum);

    cudaFuncSetAttribute(gemm_mma<0>, cudaFuncAttributeMaxDynamicSharedMemorySize, SMEM_TOTAL);
    cudaFuncSetAttribute(gemm_mma<1>, cudaFuncAttributeMaxDynamicSharedMemorySize, SMEM_TOTAL);
    cudaFuncSetAttribute(gemm_mma<2>, cudaFuncAttributeMaxDynamicSharedMemorySize, SMEM_TOTAL);

    const size_t DD = (size_t)D_DIM * D_DIM;

    convx_rowsum<<<M_DIM / 8, 256>>>(x, x16, rs);
    conv_kernel<<<(int)(4 * DD / 4 / 256), 256>>>(Ws, ws, (int)(4 * DD / 4));
    conv_kernel<<<(int)(DD / 4 / 256), 256>>>(Wo, wo, (int)(DD / 4));

    dim3 grid(D_DIM / BN, M_DIM / BM);   // (8, 128)

    gemm_mma<0><<<grid, NTH, SMEM_TOTAL>>>(x16, ws + 0 * DD, bs + 0 * D_DIM,
                                           a0, nullptr, nullptr, nullptr);
    gemm_mma<0><<<grid, NTH, SMEM_TOTAL>>>(a0, ws + 1 * DD, bs + 1 * D_DIM,
                                           a1, nullptr, nullptr, nullptr);
    gemm_mma<0><<<grid, NTH, SMEM_TOTAL>>>(a1, ws + 2 * DD, bs + 2 * D_DIM,
                                           a0, nullptr, nullptr, nullptr);
    gemm_mma<1><<<grid, NTH, SMEM_TOTAL>>>(a0, ws + 3 * DD, bs + 3 * D_DIM,
                                           a1, nullptr, x, rs);
    gemm_mma<2><<<grid, NTH, SMEM_TOTAL>>>(a1, wo, bo,
                                           nullptr, out, nullptr, nullptr);
}

// round 14
// speedup vs baseline: 3.4017x; 1.0385x over previous
#include <cuda_runtime.h>
#include <cuda_fp16.h>
#include <cstdint>

// ---------------------------------------------------------------------------
// Problem dims (fixed)
// ---------------------------------------------------------------------------
#define M_DIM 16384
#define D_DIM 1024

// GEMM tiling
#define BM 128
#define BN 256
#define BK 64                        // fp16 elements per K-stage (=128B rows)
#define NSTAGES (D_DIM / BK)         // 16
#define NBUF 3
#define NTH 256                      // 8 warps (2x4 grid, 64x64 warp tiles)

// SMEM stage layout (bytes): rows of 128B, SW128 xor-swizzled
#define A_SZ (BM * 128)              // 16384
#define B_SZ (BN * 128)              // 32768
#define OFF_A 0
#define OFF_B (A_SZ)
#define STAGE_BYTES (A_SZ + B_SZ)    // 49152
#define SMEM_TOTAL (1024 + NBUF * STAGE_BYTES)   // 148480

// ---------------------------------------------------------------------------
// Scratch (__device__ globals; no allocation allowed)
// ---------------------------------------------------------------------------
__device__ __align__(256) __half g_x16[(size_t)M_DIM * D_DIM];
__device__ __align__(256) __half g_a0[(size_t)M_DIM * D_DIM];
__device__ __align__(256) __half g_a1[(size_t)M_DIM * D_DIM];
__device__ __align__(256) __half g_ws[(size_t)4 * D_DIM * D_DIM];
__device__ __align__(256) __half g_wo[(size_t)D_DIM * D_DIM];
__device__ float g_rowsum[M_DIM];

// ---------------------------------------------------------------------------
// PTX helpers (all baseline compute_80-level)
// ---------------------------------------------------------------------------
__device__ __forceinline__ uint32_t smem_u32(const void* p) {
    uint32_t a;
    asm("{ .reg .u64 t; cvta.to.shared.u64 t, %1; cvt.u32.u64 %0, t; }"
        : "=r"(a) : "l"(p));
    return a;
}
__device__ __forceinline__ void cpa16(uint32_t dst, const void* src) {
    asm volatile("cp.async.cg.shared.global [%0], [%1], 16;" :: "r"(dst), "l"(src));
}
#define CP_COMMIT() asm volatile("cp.async.commit_group;" ::: "memory")
#define CP_WAIT1()  asm volatile("cp.async.wait_group 1;" ::: "memory")

__device__ __forceinline__ uint32_t swz(uint32_t off) {
    return off ^ ((off >> 3) & 0x70);
}
__device__ __forceinline__ void ldmx4(uint32_t* r, uint32_t addr) {
    asm volatile("ldmatrix.sync.aligned.m8n8.x4.shared.b16 {%0,%1,%2,%3}, [%4];"
                 : "=r"(r[0]), "=r"(r[1]), "=r"(r[2]), "=r"(r[3]) : "r"(addr));
}
__device__ __forceinline__ void mma16816(float* c, const uint32_t* a,
                                         const uint32_t* b) {
    asm volatile(
        "mma.sync.aligned.m16n8k16.row.col.f32.f16.f16.f32 "
        "{%0,%1,%2,%3}, {%4,%5,%6,%7}, {%8,%9}, {%0,%1,%2,%3};"
        : "+f"(c[0]), "+f"(c[1]), "+f"(c[2]), "+f"(c[3])
        : "r"(a[0]), "r"(a[1]), "r"(a[2]), "r"(a[3]), "r"(b[0]), "r"(b[1]));
}

// ---------------------------------------------------------------------------
// Small kernels: fp32 -> fp16 conversion
// ---------------------------------------------------------------------------
__global__ void conv_kernel(const float* __restrict__ s,
                            __half* __restrict__ h, int n4) {
    int i = blockIdx.x * blockDim.x + threadIdx.x;
    if (i >= n4) return;
    float4 v = reinterpret_cast<const float4*>(s)[i];
    __half2 p0 = __floats2half2_rn(v.x, v.y);
    __half2 p1 = __floats2half2_rn(v.z, v.w);
    reinterpret_cast<__half2*>(h)[i * 2 + 0] = p0;
    reinterpret_cast<__half2*>(h)[i * 2 + 1] = p1;
}

__global__ void convx_rowsum(const float* __restrict__ x,
                             __half* __restrict__ xh,
                             float* __restrict__ rs) {
    int row  = blockIdx.x * 8 + (threadIdx.x >> 5);
    int lane = threadIdx.x & 31;
    const float4* xr = reinterpret_cast<const float4*>(x + (size_t)row * D_DIM);
    __half2* dh = reinterpret_cast<__half2*>(xh + (size_t)row * D_DIM);
    float s = 0.f;
#pragma unroll
    for (int i = 0; i < 8; i++) {
        float4 v = xr[lane + i * 32];
        s += v.x + v.y + v.z + v.w;
        dh[(lane + i * 32) * 2 + 0] = __floats2half2_rn(v.x, v.y);
        dh[(lane + i * 32) * 2 + 1] = __floats2half2_rn(v.z, v.w);
    }
#pragma unroll
    for (int o = 16; o > 0; o >>= 1) s += __shfl_xor_sync(0xffffffffu, s, o);
    if (lane == 0) rs[row] = s;
}

// ---------------------------------------------------------------------------
// HMMA GEMM, 8 warps, 64x64 warp tiles, single-term fp16, fused epilogue.
// MODE 0: relu(acc+b) -> fp16;  MODE 1: +interaction -> fp16;  MODE 2: fp32
// ---------------------------------------------------------------------------
template <int MODE>
__global__ __launch_bounds__(NTH, 1)
void gemm_mma(const __half* __restrict__ A, const __half* __restrict__ W,
              const float* __restrict__ bias,
              __half* __restrict__ Oh, float* __restrict__ Of,
              const float* __restrict__ x, const float* __restrict__ rowsum)
{
    extern __shared__ char smem_raw[];
    uint32_t sb = smem_u32(smem_raw);
    sb = (sb + 1023u) & ~1023u;

    const int tid  = threadIdx.x;
    const int wid  = tid >> 5;
    const int lane = tid & 31;
    const int wm   = wid >> 2;          // 0..1  (64 rows each)
    const int wn   = wid & 3;           // 0..3  (64 cols each)
    const int n0   = blockIdx.x * BN;
    const int m0   = blockIdx.y * BM;

    // ---- hoisted loader addressing (loop-invariant per thread) ----
    const int lc = tid & 7;
    uint32_t swoA[4];
    size_t gaB[4];
#pragma unroll
    for (int i = 0; i < 4; i++) {
        int r = (tid >> 3) + i * 32;
        swoA[i] = swz((uint32_t)(r * 128 + lc * 16));
        gaB[i]  = (size_t)(m0 + r) * D_DIM + lc * 8;
    }
    uint32_t swoB[8];
    size_t gbB[8];
#pragma unroll
    for (int i = 0; i < 8; i++) {
        int r = (tid >> 3) + i * 32;
        swoB[i] = swz((uint32_t)(r * 128 + lc * 16));
        gbB[i]  = (size_t)(n0 + r) * D_DIM + lc * 8;
    }

    auto load_stage = [&](int s) {
        const uint32_t base = sb + (uint32_t)(s % NBUF) * STAGE_BYTES;
        const int kt = s * BK;
#pragma unroll
        for (int i = 0; i < 4; i++)
            cpa16(base + OFF_A + swoA[i], A + gaB[i] + kt);
#pragma unroll
        for (int i = 0; i < 8; i++)
            cpa16(base + OFF_B + swoB[i], W + gbB[i] + kt);
    };

    float acc[4][8][4];
#pragma unroll
    for (int i = 0; i < 4; i++)
#pragma unroll
        for (int j = 0; j < 8; j++)
#pragma unroll
            for (int q = 0; q < 4; q++) acc[i][j][q] = 0.f;

    load_stage(0); CP_COMMIT();
    load_stage(1); CP_COMMIT();

    // ldmatrix per-lane address components
    const uint32_t a_row = wm * 64 + (lane & 15);
    const uint32_t a_k   = (uint32_t)(lane >> 4) * 8;
    const uint32_t b_row = wn * 64 + ((uint32_t)(lane >> 4) * 8) + (lane & 7);
    const uint32_t b_k   = (uint32_t)((lane >> 3) & 1) * 8;

#pragma unroll 1
    for (int s = 0; s < NSTAGES; s++) {
        CP_WAIT1();                 // stage s resident (s+1 may be in flight)
        __syncthreads();            // data visible; stage s-1 readers retired

        const uint32_t base = sb + (uint32_t)(s % NBUF) * STAGE_BYTES;
#pragma unroll
        for (int ks = 0; ks < 4; ks++) {
            const uint32_t kk = ks * 16;
            uint32_t ah[4][4], bh[4][4];
#pragma unroll
            for (int mt = 0; mt < 4; mt++) {
                uint32_t sw = swz((a_row + mt * 16) * 128 + (kk + a_k) * 2);
                ldmx4(ah[mt], base + OFF_A + sw);
            }
#pragma unroll
            for (int nb = 0; nb < 4; nb++) {
                uint32_t sw = swz((b_row + nb * 16) * 128 + (kk + b_k) * 2);
                ldmx4(bh[nb], base + OFF_B + sw);
            }
#pragma unroll
            for (int mt = 0; mt < 4; mt++)
#pragma unroll
                for (int nt = 0; nt < 8; nt++) {
                    mma16816(acc[mt][nt], ah[mt], &bh[nt >> 1][(nt & 1) * 2]);
                }
        }

        // Issue next prefetch AFTER compute (buffer (s+2)%3 freed at barrier)
        if (s + 2 < NSTAGES) { load_stage(s + 2); CP_COMMIT(); }
    }

    // ---- epilogue ----
    const int qrow = lane >> 2;          // 0..7
    const int qcol = (lane & 3) * 2;     // 0,2,4,6
#pragma unroll
    for (int mt = 0; mt < 4; mt++) {
#pragma unroll
        for (int half = 0; half < 2; half++) {
            const int gm = m0 + wm * 64 + mt * 16 + qrow + half * 8;
            float rsv = 0.f;
            if (MODE == 1) rsv = rowsum[gm];
#pragma unroll
            for (int nt = 0; nt < 8; nt++) {
                const int gn = n0 + wn * 64 + nt * 8 + qcol;
                const float2 bv = *reinterpret_cast<const float2*>(bias + gn);
                float v0 = acc[mt][nt][half * 2 + 0] + bv.x;
                float v1 = acc[mt][nt][half * 2 + 1] + bv.y;
                if (MODE == 2) {
                    *reinterpret_cast<float2*>(Of + (size_t)gm * D_DIM + gn) =
                        make_float2(v0, v1);
                } else {
                    v0 = fmaxf(v0, 0.f);
                    v1 = fmaxf(v1, 0.f);
                    if (MODE == 1) {
                        const float2 xv = *reinterpret_cast<const float2*>(
                            x + (size_t)gm * D_DIM + gn);
                        v0 = (v0 + fmaxf(xv.x * rsv, 0.f)) * 0.5f;
                        v1 = (v1 + fmaxf(xv.y * rsv, 0.f)) * 0.5f;
                    }
                    *reinterpret_cast<__half2*>(Oh + (size_t)gm * D_DIM + gn) =
                        __floats2half2_rn(v0, v1);
                }
            }
        }
    }
}

// ---------------------------------------------------------------------------
// Launch
// ---------------------------------------------------------------------------
extern "C" void kernel_launch(void* const* d_in, const int* in_sizes, int n_in,
                              void* d_out, int out_size) {
    const float* x  = (const float*)d_in[0];
    const float* Ws = (const float*)d_in[1];   // (4, D, D)
    const float* bs = (const float*)d_in[2];   // (4, D)
    const float* Wo = (const float*)d_in[3];   // (D, D)
    const float* bo = (const float*)d_in[4];   // (D,)
    float* out = (float*)d_out;

    __half *x16, *a0, *a1, *ws, *wo;
    float* rs;
    cudaGetSymbolAddress((void**)&x16, g_x16);
    cudaGetSymbolAddress((void**)&a0,  g_a0);
    cudaGetSymbolAddress((void**)&a1,  g_a1);
    cudaGetSymbolAddress((void**)&ws,  g_ws);
    cudaGetSymbolAddress((void**)&wo,  g_wo);
    cudaGetSymbolAddress((void**)&rs,  g_rowsum);

    cudaFuncSetAttribute(gemm_mma<0>, cudaFuncAttributeMaxDynamicSharedMemorySize, SMEM_TOTAL);
    cudaFuncSetAttribute(gemm_mma<1>, cudaFuncAttributeMaxDynamicSharedMemorySize, SMEM_TOTAL);
    cudaFuncSetAttribute(gemm_mma<2>, cudaFuncAttributeMaxDynamicSharedMemorySize, SMEM_TOTAL);

    const size_t DD = (size_t)D_DIM * D_DIM;

    convx_rowsum<<<M_DIM / 8, 256>>>(x, x16, rs);
    conv_kernel<<<(int)(4 * DD / 4 / 256), 256>>>(Ws, ws, (int)(4 * DD / 4));
    conv_kernel<<<(int)(DD / 4 / 256), 256>>>(Wo, wo, (int)(DD / 4));

    dim3 grid(D_DIM / BN, M_DIM / BM);   // (4, 128)

    gemm_mma<0><<<grid, NTH, SMEM_TOTAL>>>(x16, ws + 0 * DD, bs + 0 * D_DIM,
                                           a0, nullptr, nullptr, nullptr);
    gemm_mma<0><<<grid, NTH, SMEM_TOTAL>>>(a0, ws + 1 * DD, bs + 1 * D_DIM,
                                           a1, nullptr, nullptr, nullptr);
    gemm_mma<0><<<grid, NTH, SMEM_TOTAL>>>(a1, ws + 2 * DD, bs + 2 * D_DIM,
                                           a0, nullptr, nullptr, nullptr);
    gemm_mma<1><<<grid, NTH, SMEM_TOTAL>>>(a0, ws + 3 * DD, bs + 3 * D_DIM,
                                           a1, nullptr, x, rs);
    gemm_mma<2><<<grid, NTH, SMEM_TOTAL>>>(a1, wo, bo,
                                           nullptr, out, nullptr, nullptr);
}